// round 14
// baseline (speedup 1.0000x reference)
#include <cuda_runtime.h>
#include <cuda_bf16.h>
#include <cstdint>

#define NUM_GRAPHS 512
#define C 128
#define CG (C / 4)           // 32 channel-groups of float4
#define THREADS 512
#define RPI (THREADS / CG)   // 16 rows per iteration
#define EPS 1e-5f
#define GRID 256
#define NSEG (NUM_GRAPHS / GRID)   // 2 segments per CTA

// Interpolation-guess + gallop: first idx with batch[idx] >= g.
__device__ __forceinline__ int find_bound(const int* __restrict__ batch, int n, int g) {
    if (g <= 0) return 0;
    int p = (int)(((long long)g * (long long)n) >> 9);
    if (p > n) p = n;
    int wlo = p, s = 512;
    while (wlo > 0 && batch[wlo - 1] >= g) { wlo -= s; if (wlo < 0) wlo = 0; s <<= 1; }
    int whi = p; s = 512;
    while (whi < n && batch[whi] < g)      { whi += s; if (whi > n) whi = n; s <<= 1; }
    while (wlo < whi) {
        int mid = (wlo + whi) >> 1;
        if (batch[mid] < g) wlo = mid + 1; else whi = mid;
    }
    return wlo;
}

#define ACC(v) do { \
    s0 += (v).x; s1 += (v).y; s2 += (v).z; s3 += (v).w; \
    q0 += (v).x * (v).x; q1 += (v).y * (v).y; \
    q2 += (v).z * (v).z; q3 += (v).w * (v).w; } while (0)

#define NORM_ST(v, idx) do { \
    (v).x = ((v).x - m.x) * iv.x * wv.x + bv.x; \
    (v).y = ((v).y - m.y) * iv.y * wv.y + bv.y; \
    (v).z = ((v).z - m.z) * iv.z * wv.z + bv.z; \
    (v).w = ((v).w - m.w) * iv.w * wv.w + bv.w; \
    __stcs(&op[(size_t)(idx) * CG + cg], (v)); } while (0)

__global__ __launch_bounds__(THREADS, 2)
void graphnorm_kernel(const float* __restrict__ x,
                      const int*   __restrict__ batch,
                      const float* __restrict__ weight,
                      const float* __restrict__ bias,
                      float* __restrict__ out,
                      int n) {
    const int t  = threadIdx.x;
    const int cg = t & (CG - 1);   // channel group (4 consecutive channels)
    const int rw = t >> 5;         // row lane (0..15)

    __shared__ int   s_bound[2 * NSEG];
    __shared__ float s_sum[RPI][C];   // 8 KB
    __shared__ float s_sq [RPI][C];   // 8 KB
    __shared__ float s_mean[C];
    __shared__ float s_inv [C];

    // ---- fused boundary search: one 977-row segment per round, 2 rounds ----
    if (t < 2 * NSEG) {
        const int g = blockIdx.x + (t >> 1) * GRID + (t & 1);
        s_bound[t] = find_bound(batch, n, g);
    }

    const float4 wv = ((const float4*)weight)[cg];
    const float4 bv = ((const float4*)bias)[cg];
    const float4* __restrict__ xp = (const float4*)x;
    float4* __restrict__       op = (float4*)out;

    __syncthreads();

    for (int i = 0; i < NSEG; i++) {
        const int start = s_bound[2 * i];
        const int end   = s_bound[2 * i + 1];
        const int cnt   = end - start;

        // ---- pass 1 (ascending, 4-unrolled): whole segment, plain cached loads ----
        float s0 = 0.f, s1 = 0.f, s2 = 0.f, s3 = 0.f;
        float q0 = 0.f, q1 = 0.f, q2 = 0.f, q3 = 0.f;
        int r = start + rw;
        for (; r + 3 * RPI < end; r += 4 * RPI) {
            float4 a = xp[(size_t)r * CG + cg];
            float4 b = xp[(size_t)(r + 1 * RPI) * CG + cg];
            float4 c = xp[(size_t)(r + 2 * RPI) * CG + cg];
            float4 d = xp[(size_t)(r + 3 * RPI) * CG + cg];
            ACC(a); ACC(b); ACC(c); ACC(d);
        }
        for (; r < end; r += RPI) {
            float4 v = xp[(size_t)r * CG + cg];
            ACC(v);
        }
        s_sum[rw][cg * 4 + 0] = s0; s_sum[rw][cg * 4 + 1] = s1;
        s_sum[rw][cg * 4 + 2] = s2; s_sum[rw][cg * 4 + 3] = s3;
        s_sq [rw][cg * 4 + 0] = q0; s_sq [rw][cg * 4 + 1] = q1;
        s_sq [rw][cg * 4 + 2] = q2; s_sq [rw][cg * 4 + 3] = q3;
        __syncthreads();

        // ---- cross-lane reduction (warp 0, fixed order => deterministic) ----
        if (rw == 0) {
            float S0 = 0.f, S1 = 0.f, S2 = 0.f, S3 = 0.f;
            float Q0 = 0.f, Q1 = 0.f, Q2 = 0.f, Q3 = 0.f;
            #pragma unroll
            for (int k = 0; k < RPI; k++) {
                S0 += s_sum[k][cg * 4 + 0]; S1 += s_sum[k][cg * 4 + 1];
                S2 += s_sum[k][cg * 4 + 2]; S3 += s_sum[k][cg * 4 + 3];
                Q0 += s_sq [k][cg * 4 + 0]; Q1 += s_sq [k][cg * 4 + 1];
                Q2 += s_sq [k][cg * 4 + 2]; Q3 += s_sq [k][cg * 4 + 3];
            }
            const float invc = 1.0f / (float)max(cnt, 1);
            float m0 = S0 * invc, m1 = S1 * invc, m2 = S2 * invc, m3 = S3 * invc;
            float v0 = Q0 * invc - m0 * m0;
            float v1 = Q1 * invc - m1 * m1;
            float v2 = Q2 * invc - m2 * m2;
            float v3 = Q3 * invc - m3 * m3;
            s_mean[cg * 4 + 0] = m0; s_mean[cg * 4 + 1] = m1;
            s_mean[cg * 4 + 2] = m2; s_mean[cg * 4 + 3] = m3;
            s_inv [cg * 4 + 0] = rsqrtf(v0 + EPS);
            s_inv [cg * 4 + 1] = rsqrtf(v1 + EPS);
            s_inv [cg * 4 + 2] = rsqrtf(v2 + EPS);
            s_inv [cg * 4 + 3] = rsqrtf(v3 + EPS);
        }
        __syncthreads();

        const float4 m  = ((const float4*)s_mean)[cg];
        const float4 iv = ((const float4*)s_inv)[cg];

        // ---- pass 2 (DESCENDING): read most-recent lines first, so the lines LRU
        //      evicted during pass-1 (the oldest = segment front) are needed last ----
        const int rbeg = start + rw;
        const int span = end - rbeg;
        const int nIt  = (span > 0) ? ((span + RPI - 1) / RPI) : 0;
        const int nF   = nIt >> 2;
        for (int k = nIt - 1; k >= nF * 4; k--) {   // tail singles (top rows first)
            int rr = rbeg + k * RPI;
            float4 v = __ldcs(&xp[(size_t)rr * CG + cg]);
            NORM_ST(v, rr);
        }
        for (int f = nF - 1; f >= 0; f--) {         // full 4-blocks, descending
            int rr = rbeg + 4 * f * RPI;
            float4 a = __ldcs(&xp[(size_t)(rr + 3 * RPI) * CG + cg]);
            float4 b = __ldcs(&xp[(size_t)(rr + 2 * RPI) * CG + cg]);
            float4 c = __ldcs(&xp[(size_t)(rr + 1 * RPI) * CG + cg]);
            float4 d = __ldcs(&xp[(size_t)rr * CG + cg]);
            NORM_ST(a, rr + 3 * RPI);
            NORM_ST(b, rr + 2 * RPI);
            NORM_ST(c, rr + 1 * RPI);
            NORM_ST(d, rr);
        }
        __syncthreads();   // protect s_sum/s_mean before next round's writes
    }
}

extern "C" void kernel_launch(void* const* d_in, const int* in_sizes, int n_in,
                              void* d_out, int out_size) {
    const float* x      = (const float*)d_in[0];
    const int*   batch  = (const int*)d_in[1];
    const float* weight = (const float*)d_in[2];
    const float* bias   = (const float*)d_in[3];
    float*       out    = (float*)d_out;
    const int n = in_sizes[1];

    graphnorm_kernel<<<GRID, THREADS>>>(x, batch, weight, bias, out, n);
}